// round 4
// baseline (speedup 1.0000x reference)
#include <cuda_runtime.h>
#include <cuda_bf16.h>
#include <cstdint>
#include <cstddef>

// ============================================================================
// Problem: B=4, S=4096, E=1024, H=16, D=64.  out = proj(attn over heads)
// Compile target is compute_100 PTX (no 'a' suffix) -> tcgen05 unavailable
// (proven by Round-1 ptxas errors). Tensor path: mma.sync.m16n8k16 bf16
// (HMMA) + ldmatrix + cp.async. fp32 accuracy recovered via 3-term bf16
// split (hi*hi + hi*lo + lo*hi), combined rel. precision ~2^-16.
//
// NOTE: resubmission of the Round-3 kernel. Rounds 0/2/3 died with
// "GB300 container failed twice" (Round 0 = unmodified stub -> infra flake,
// not kernel-induced). Kernel statically audited: fragment layouts, bank-
// conflict-free 80B row padding, bounded indices, terminating cp.async
// pipeline, 40KB static smem, graph-capturable launcher.
// ============================================================================
static constexpr int MROWS = 16384;          // B*S
static constexpr int EDIM  = 1024;
static constexpr size_t ACT_ELEMS = (size_t)MROWS * EDIM;
static constexpr size_t W_ELEMS   = (size_t)EDIM * EDIM;

// ---------------------------------------------------------------------------
// Scratch (__device__ globals; no allocation allowed)
// ---------------------------------------------------------------------------
__device__ __nv_bfloat16 g_xhi[ACT_ELEMS];
__device__ __nv_bfloat16 g_xlo[ACT_ELEMS];
__device__ __nv_bfloat16 g_whi[4 * W_ELEMS];
__device__ __nv_bfloat16 g_wlo[4 * W_ELEMS];
__device__ float g_Q[ACT_ELEMS];
__device__ float g_K[ACT_ELEMS];
__device__ float g_V[ACT_ELEMS];
__device__ __nv_bfloat16 g_ahi[ACT_ELEMS];
__device__ __nv_bfloat16 g_alo[ACT_ELEMS];

// ---------------------------------------------------------------------------
// PTX helpers (base-target features only)
// ---------------------------------------------------------------------------
__device__ __forceinline__ uint32_t smem_to_u32(const void* smem_ptr) {
    uint32_t addr;
    asm("{ .reg .u64 tmp; cvta.to.shared.u64 tmp, %1; cvt.u32.u64 %0, tmp; }"
        : "=r"(addr) : "l"(smem_ptr));
    return addr;
}

__device__ __forceinline__ void cp16(uint32_t dst, const void* src) {
    asm volatile("cp.async.cg.shared.global [%0], [%1], 16;"
                 :: "r"(dst), "l"(src));
}
__device__ __forceinline__ void cp_commit() {
    asm volatile("cp.async.commit_group;");
}
__device__ __forceinline__ void cp_wait1() {
    asm volatile("cp.async.wait_group 1;");
}
__device__ __forceinline__ void cp_wait0() {
    asm volatile("cp.async.wait_group 0;");
}

__device__ __forceinline__ void ldm_x4(uint32_t* r, uint32_t addr) {
    asm volatile("ldmatrix.sync.aligned.m8n8.x4.shared.b16 {%0,%1,%2,%3}, [%4];"
                 : "=r"(r[0]), "=r"(r[1]), "=r"(r[2]), "=r"(r[3]) : "r"(addr));
}

__device__ __forceinline__ void mma_16816(float* c, const uint32_t* a, const uint32_t* b) {
    asm volatile(
        "mma.sync.aligned.m16n8k16.row.col.f32.bf16.bf16.f32 "
        "{%0,%1,%2,%3}, {%4,%5,%6,%7}, {%8,%9}, {%0,%1,%2,%3};"
        : "+f"(c[0]), "+f"(c[1]), "+f"(c[2]), "+f"(c[3])
        : "r"(a[0]), "r"(a[1]), "r"(a[2]), "r"(a[3]), "r"(b[0]), "r"(b[1]));
}

// ============================================================================
// Split: fp32 -> bf16 hi + lo (x ~= hi + lo; combined precision ~2^-16)
// ============================================================================
__global__ void split_kernel(const float4* __restrict__ in,
                             __nv_bfloat16* __restrict__ hi,
                             __nv_bfloat16* __restrict__ lo, int n4) {
    for (int i = blockIdx.x * blockDim.x + threadIdx.x; i < n4;
         i += gridDim.x * blockDim.x) {
        float4 v = in[i];
        __nv_bfloat16 h0 = __float2bfloat16(v.x);
        __nv_bfloat16 h1 = __float2bfloat16(v.y);
        __nv_bfloat16 h2 = __float2bfloat16(v.z);
        __nv_bfloat16 h3 = __float2bfloat16(v.w);
        __nv_bfloat16 l0 = __float2bfloat16(v.x - __bfloat162float(h0));
        __nv_bfloat16 l1 = __float2bfloat16(v.y - __bfloat162float(h1));
        __nv_bfloat16 l2 = __float2bfloat16(v.z - __bfloat162float(h2));
        __nv_bfloat16 l3 = __float2bfloat16(v.w - __bfloat162float(h3));
        __nv_bfloat162 hA; hA.x = h0; hA.y = h1;
        __nv_bfloat162 hB; hB.x = h2; hB.y = h3;
        __nv_bfloat162 lA; lA.x = l0; lA.y = l1;
        __nv_bfloat162 lB; lB.x = l2; lB.y = l3;
        ((__nv_bfloat162*)hi)[2 * i]     = hA;
        ((__nv_bfloat162*)hi)[2 * i + 1] = hB;
        ((__nv_bfloat162*)lo)[2 * i]     = lA;
        ((__nv_bfloat162*)lo)[2 * i + 1] = lB;
    }
}

// ============================================================================
// GEMM: C[M,1024] = A[M,1024] @ W[1024,1024]^T + bias via 3-term bf16 split.
// CTA 128x128, BK=32, 256 thr, warp tile 32x64, cp.async double buffer.
// Smem rows padded to 80B: {80*r mod 128} = {0,80,32,112,64,16,96,48} ->
// all 8 distinct 16B slots -> conflict-free ldmatrix without XOR swizzle.
// blockIdx.z selects among up to 3 fused (W, bias, C) problem instances
// sharing the same A operand (Q/K/V projections).
// ============================================================================
static constexpr int BM = 128, BN = 128, BK = 32;
static constexpr int ROWB = 80;                   // padded row stride (bytes)
static constexpr int TILE_B = 128 * ROWB;         // 10240 B per tile
static constexpr int STAGE_B = 2 * TILE_B;        // A + B per stage
static constexpr int NCHUNK = EDIM / BK;          // 32
static constexpr int NIT = 3 * NCHUNK;            // 96 (3 split terms)

struct GemmJob {
    const __nv_bfloat16* Whi;
    const __nv_bfloat16* Wlo;
    const float* bias;
    float* C;
};

__global__ void __launch_bounds__(256)
gemm_split_kernel(const __nv_bfloat16* __restrict__ Ahi,
                  const __nv_bfloat16* __restrict__ Alo,
                  GemmJob j0, GemmJob j1, GemmJob j2) {
    const GemmJob job = (blockIdx.z == 0) ? j0 : (blockIdx.z == 1) ? j1 : j2;
    const __nv_bfloat16* __restrict__ Bhi = job.Whi;
    const __nv_bfloat16* __restrict__ Blo = job.Wlo;
    const float* __restrict__ bias = job.bias;
    float* __restrict__ C = job.C;

    __shared__ __align__(128) unsigned char smem[2 * STAGE_B];   // 40 KB
    const uint32_t sbase = smem_to_u32(smem);
    const int tid  = threadIdx.x;
    const int lane = tid & 31;
    const int w    = tid >> 5;
    const int m_off = (w >> 1) * 32;
    const int n_off = (w & 1) * 64;
    const int m0 = blockIdx.y * BM;
    const int n0 = blockIdx.x * BN;

    // ---- prefetch -------------------------------------------------------
    auto prefetch = [&](int it, int stage) {
        const int term = it >> 5;                 // /NCHUNK
        const int kc   = it & 31;
        const __nv_bfloat16* Ag = (term == 2) ? Alo : Ahi;   // hi,hi,lo
        const __nv_bfloat16* Bg = (term == 1) ? Blo : Bhi;   // hi,lo,hi
        const uint32_t sA = sbase + stage * STAGE_B;
        const uint32_t sB = sA + TILE_B;
        #pragma unroll
        for (int rep = 0; rep < 2; rep++) {
            int idx = tid + rep * 256;            // 0..511
            int r   = idx >> 2;                   // row 0..127
            int s   = idx & 3;                    // 16B segment
            cp16(sA + r * ROWB + s * 16,
                 Ag + (size_t)(m0 + r) * EDIM + kc * BK + s * 8);
            cp16(sB + r * ROWB + s * 16,
                 Bg + (size_t)(n0 + r) * EDIM + kc * BK + s * 8);
        }
        cp_commit();
    };

    float c[2][8][4];
    #pragma unroll
    for (int mi = 0; mi < 2; mi++)
        #pragma unroll
        for (int ni = 0; ni < 8; ni++)
            #pragma unroll
            for (int q = 0; q < 4; q++) c[mi][ni][q] = 0.f;

    prefetch(0, 0);

    for (int it = 0; it < NIT; it++) {
        if (it + 1 < NIT) {
            prefetch(it + 1, (it + 1) & 1);
            cp_wait1();
        } else {
            cp_wait0();
        }
        __syncthreads();

        const uint32_t sA = sbase + (it & 1) * STAGE_B;
        const uint32_t sB = sA + TILE_B;

        #pragma unroll
        for (int ks = 0; ks < 2; ks++) {          // two k16 steps in BK=32
            uint32_t a[2][4];
            #pragma unroll
            for (int mi = 0; mi < 2; mi++) {
                uint32_t addr = sA + (m_off + mi * 16 + (lane & 15)) * ROWB
                              + ks * 32 + ((lane >> 4) & 1) * 16;
                ldm_x4(a[mi], addr);
            }
            uint32_t b[8][2];
            #pragma unroll
            for (int ni = 0; ni < 4; ni++) {
                uint32_t r4[4];
                uint32_t addr = sB + (n_off + ni * 16 + ((lane >> 4) << 3) + (lane & 7)) * ROWB
                              + ks * 32 + ((lane >> 3) & 1) * 16;
                ldm_x4(r4, addr);
                b[2 * ni][0]     = r4[0]; b[2 * ni][1]     = r4[1];
                b[2 * ni + 1][0] = r4[2]; b[2 * ni + 1][1] = r4[3];
            }
            #pragma unroll
            for (int mi = 0; mi < 2; mi++)
                #pragma unroll
                for (int ni = 0; ni < 8; ni++)
                    mma_16816(c[mi][ni], a[mi], b[ni]);
        }
        __syncthreads();
    }

    // ---- epilogue: add bias, write fp32 ---------------------------------
    const int row0 = m0 + m_off + (lane >> 2);
    const int col0 = n0 + n_off + (lane & 3) * 2;
    #pragma unroll
    for (int ni = 0; ni < 8; ni++) {
        const int cL = col0 + ni * 8;
        const float b0 = bias[cL], b1 = bias[cL + 1];
        #pragma unroll
        for (int mi = 0; mi < 2; mi++) {
            const int r = row0 + mi * 16;
            float2 v0; v0.x = c[mi][ni][0] + b0; v0.y = c[mi][ni][1] + b1;
            *(float2*)(C + (size_t)r * EDIM + cL) = v0;
            float2 v1; v1.x = c[mi][ni][2] + b0; v1.y = c[mi][ni][3] + b1;
            *(float2*)(C + (size_t)(r + 8) * EDIM + cL) = v1;
        }
    }
}

// ============================================================================
// Attention: per position, scores = q k^T / 8 over the 16 heads, softmax,
// out = w v. One warp per position; output emitted as bf16 hi/lo split.
// ============================================================================
__global__ void __launch_bounds__(128)
attn_kernel(const float* __restrict__ Q, const float* __restrict__ K,
            const float* __restrict__ V,
            __nv_bfloat16* __restrict__ Ohi, __nv_bfloat16* __restrict__ Olo) {
    __shared__ float sk[4][1024];
    __shared__ float sv[4][1024];
    int w = threadIdx.x >> 5, lid = threadIdx.x & 31;
    int p = blockIdx.x * 4 + w;

    const float* kp = K + (size_t)p * 1024;
    const float* vp = V + (size_t)p * 1024;
    #pragma unroll
    for (int j = 0; j < 8; j++) {
        int idx = lid + j * 32;
        ((float4*)sk[w])[idx] = ((const float4*)kp)[idx];
        ((float4*)sv[w])[idx] = ((const float4*)vp)[idx];
    }
    __syncwarp();

    float wgt[16];
    #pragma unroll
    for (int j = 0; j < 16; j++) wgt[j] = 0.f;

    if (lid < 16) {
        const float* qp = Q + (size_t)p * 1024 + lid * 64;
        float q[64];
        #pragma unroll
        for (int j = 0; j < 16; j++) {
            float4 t = ((const float4*)qp)[j];
            q[4 * j] = t.x; q[4 * j + 1] = t.y; q[4 * j + 2] = t.z; q[4 * j + 3] = t.w;
        }
        float mx = -1e30f;
        #pragma unroll
        for (int j = 0; j < 16; j++) {
            float acc = 0.f;
            #pragma unroll
            for (int d4 = 0; d4 < 16; d4++) {
                float4 kv = ((const float4*)(&sk[w][j * 64]))[d4];
                acc += q[4 * d4] * kv.x + q[4 * d4 + 1] * kv.y
                     + q[4 * d4 + 2] * kv.z + q[4 * d4 + 3] * kv.w;
            }
            wgt[j] = acc * 0.125f;
            mx = fmaxf(mx, wgt[j]);
        }
        float sum = 0.f;
        #pragma unroll
        for (int j = 0; j < 16; j++) { wgt[j] = __expf(wgt[j] - mx); sum += wgt[j]; }
        float inv = 1.f / sum;
        #pragma unroll
        for (int j = 0; j < 16; j++) wgt[j] *= inv;
    }
    __syncwarp();

    int i = lid & 15;
    int dbase = (lid >> 4) * 32;
    float o[32];
    #pragma unroll
    for (int d = 0; d < 32; d++) o[d] = 0.f;
    #pragma unroll
    for (int j = 0; j < 16; j++) {
        float wj = __shfl_sync(0xffffffffu, wgt[j], i);
        #pragma unroll
        for (int d4 = 0; d4 < 8; d4++) {
            float4 vv = ((const float4*)(&sv[w][j * 64 + dbase]))[d4];
            o[4 * d4]     += wj * vv.x;
            o[4 * d4 + 1] += wj * vv.y;
            o[4 * d4 + 2] += wj * vv.z;
            o[4 * d4 + 3] += wj * vv.w;
        }
    }
    size_t ob = (size_t)p * 1024 + i * 64 + dbase;
    #pragma unroll
    for (int d2 = 0; d2 < 16; d2++) {
        float v0 = o[2 * d2], v1 = o[2 * d2 + 1];
        __nv_bfloat16 h0 = __float2bfloat16(v0);
        __nv_bfloat16 h1 = __float2bfloat16(v1);
        __nv_bfloat16 l0 = __float2bfloat16(v0 - __bfloat162float(h0));
        __nv_bfloat16 l1 = __float2bfloat16(v1 - __bfloat162float(h1));
        __nv_bfloat162 hh; hh.x = h0; hh.y = h1;
        __nv_bfloat162 ll; ll.x = l0; ll.y = l1;
        ((__nv_bfloat162*)(Ohi + ob))[d2] = hh;
        ((__nv_bfloat162*)(Olo + ob))[d2] = ll;
    }
}

// ============================================================================
// Launcher
// ============================================================================
extern "C" void kernel_launch(void* const* d_in, const int* in_sizes, int n_in,
                              void* d_out, int out_size) {
    const float* x  = (const float*)d_in[0];
    const float* wq = (const float*)d_in[1];
    const float* bq = (const float*)d_in[2];
    const float* wk = (const float*)d_in[3];
    const float* bk = (const float*)d_in[4];
    const float* wv = (const float*)d_in[5];
    const float* bv = (const float*)d_in[6];
    const float* wo = (const float*)d_in[7];
    const float* bo = (const float*)d_in[8];

    void *p;
    cudaGetSymbolAddress(&p, g_xhi); __nv_bfloat16* xhi = (__nv_bfloat16*)p;
    cudaGetSymbolAddress(&p, g_xlo); __nv_bfloat16* xlo = (__nv_bfloat16*)p;
    cudaGetSymbolAddress(&p, g_whi); __nv_bfloat16* whi = (__nv_bfloat16*)p;
    cudaGetSymbolAddress(&p, g_wlo); __nv_bfloat16* wlo = (__nv_bfloat16*)p;
    cudaGetSymbolAddress(&p, g_Q);   float* Qf = (float*)p;
    cudaGetSymbolAddress(&p, g_K);   float* Kf = (float*)p;
    cudaGetSymbolAddress(&p, g_V);   float* Vf = (float*)p;
    cudaGetSymbolAddress(&p, g_ahi); __nv_bfloat16* ahi = (__nv_bfloat16*)p;
    cudaGetSymbolAddress(&p, g_alo); __nv_bfloat16* alo = (__nv_bfloat16*)p;

    // 1. fp32 -> bf16 hi/lo splits
    split_kernel<<<2048, 256>>>((const float4*)x,  xhi, xlo, (int)(ACT_ELEMS / 4));
    split_kernel<<<512, 256>>>((const float4*)wq, whi + 0 * W_ELEMS, wlo + 0 * W_ELEMS, (int)(W_ELEMS / 4));
    split_kernel<<<512, 256>>>((const float4*)wk, whi + 1 * W_ELEMS, wlo + 1 * W_ELEMS, (int)(W_ELEMS / 4));
    split_kernel<<<512, 256>>>((const float4*)wv, whi + 2 * W_ELEMS, wlo + 2 * W_ELEMS, (int)(W_ELEMS / 4));
    split_kernel<<<512, 256>>>((const float4*)wo, whi + 3 * W_ELEMS, wlo + 3 * W_ELEMS, (int)(W_ELEMS / 4));

    // 2. Q/K/V projections fused into one launch (grid.z selects job);
    //    shared A tiles triple their L2 reuse across the three jobs.
    GemmJob jq{whi + 0 * W_ELEMS, wlo + 0 * W_ELEMS, bq, Qf};
    GemmJob jk{whi + 1 * W_ELEMS, wlo + 1 * W_ELEMS, bk, Kf};
    GemmJob jv{whi + 2 * W_ELEMS, wlo + 2 * W_ELEMS, bv, Vf};
    dim3 grid_qkv(EDIM / BN, MROWS / BM, 3);   // (8, 128, 3)
    gemm_split_kernel<<<grid_qkv, 256>>>(xhi, xlo, jq, jk, jv);

    // 3. Cross-head attention per position
    attn_kernel<<<MROWS / 4, 128>>>(Qf, Kf, Vf, ahi, alo);

    // 4. Output projection -> fp32 d_out
    GemmJob jo{whi + 3 * W_ELEMS, wlo + 3 * W_ELEMS, bo, (float*)d_out};
    dim3 grid_o(EDIM / BN, MROWS / BM, 1);
    gemm_split_kernel<<<grid_o, 256>>>(ahi, alo, jo, jo, jo);
}

// round 5
// speedup vs baseline: 1.0012x; 1.0012x over previous
#include <cuda_runtime.h>
#include <cuda_bf16.h>
#include <cstdint>
#include <cstddef>

// ============================================================================
// Problem: B=4, S=4096, E=1024, H=16, D=64.  out = proj(attn over heads)
// Compile target is compute_100 PTX (no 'a' suffix) -> tcgen05 unavailable
// (proven by Round-1 ptxas errors). Tensor path: mma.sync.m16n8k16 bf16
// (HMMA) + ldmatrix + cp.async. fp32 accuracy recovered via 3-term bf16
// split (hi*hi + hi*lo + lo*hi), combined rel. precision ~2^-16.
//
// NOTE: resubmission of the Round-3 kernel. Rounds 0/2/3 died with
// "GB300 container failed twice" (Round 0 = unmodified stub -> infra flake,
// not kernel-induced). Kernel statically audited: fragment layouts, bank-
// conflict-free 80B row padding, bounded indices, terminating cp.async
// pipeline, 40KB static smem, graph-capturable launcher.
// ============================================================================
static constexpr int MROWS = 16384;          // B*S
static constexpr int EDIM  = 1024;
static constexpr size_t ACT_ELEMS = (size_t)MROWS * EDIM;
static constexpr size_t W_ELEMS   = (size_t)EDIM * EDIM;

// ---------------------------------------------------------------------------
// Scratch (__device__ globals; no allocation allowed)
// ---------------------------------------------------------------------------
__device__ __nv_bfloat16 g_xhi[ACT_ELEMS];
__device__ __nv_bfloat16 g_xlo[ACT_ELEMS];
__device__ __nv_bfloat16 g_whi[4 * W_ELEMS];
__device__ __nv_bfloat16 g_wlo[4 * W_ELEMS];
__device__ float g_Q[ACT_ELEMS];
__device__ float g_K[ACT_ELEMS];
__device__ float g_V[ACT_ELEMS];
__device__ __nv_bfloat16 g_ahi[ACT_ELEMS];
__device__ __nv_bfloat16 g_alo[ACT_ELEMS];

// ---------------------------------------------------------------------------
// PTX helpers (base-target features only)
// ---------------------------------------------------------------------------
__device__ __forceinline__ uint32_t smem_to_u32(const void* smem_ptr) {
    uint32_t addr;
    asm("{ .reg .u64 tmp; cvta.to.shared.u64 tmp, %1; cvt.u32.u64 %0, tmp; }"
        : "=r"(addr) : "l"(smem_ptr));
    return addr;
}

__device__ __forceinline__ void cp16(uint32_t dst, const void* src) {
    asm volatile("cp.async.cg.shared.global [%0], [%1], 16;"
                 :: "r"(dst), "l"(src));
}
__device__ __forceinline__ void cp_commit() {
    asm volatile("cp.async.commit_group;");
}
__device__ __forceinline__ void cp_wait1() {
    asm volatile("cp.async.wait_group 1;");
}
__device__ __forceinline__ void cp_wait0() {
    asm volatile("cp.async.wait_group 0;");
}

__device__ __forceinline__ void ldm_x4(uint32_t* r, uint32_t addr) {
    asm volatile("ldmatrix.sync.aligned.m8n8.x4.shared.b16 {%0,%1,%2,%3}, [%4];"
                 : "=r"(r[0]), "=r"(r[1]), "=r"(r[2]), "=r"(r[3]) : "r"(addr));
}

__device__ __forceinline__ void mma_16816(float* c, const uint32_t* a, const uint32_t* b) {
    asm volatile(
        "mma.sync.aligned.m16n8k16.row.col.f32.bf16.bf16.f32 "
        "{%0,%1,%2,%3}, {%4,%5,%6,%7}, {%8,%9}, {%0,%1,%2,%3};"
        : "+f"(c[0]), "+f"(c[1]), "+f"(c[2]), "+f"(c[3])
        : "r"(a[0]), "r"(a[1]), "r"(a[2]), "r"(a[3]), "r"(b[0]), "r"(b[1]));
}

// ============================================================================
// Split: fp32 -> bf16 hi + lo (x ~= hi + lo; combined precision ~2^-16)
// ============================================================================
__global__ void split_kernel(const float4* __restrict__ in,
                             __nv_bfloat16* __restrict__ hi,
                             __nv_bfloat16* __restrict__ lo, int n4) {
    for (int i = blockIdx.x * blockDim.x + threadIdx.x; i < n4;
         i += gridDim.x * blockDim.x) {
        float4 v = in[i];
        __nv_bfloat16 h0 = __float2bfloat16(v.x);
        __nv_bfloat16 h1 = __float2bfloat16(v.y);
        __nv_bfloat16 h2 = __float2bfloat16(v.z);
        __nv_bfloat16 h3 = __float2bfloat16(v.w);
        __nv_bfloat16 l0 = __float2bfloat16(v.x - __bfloat162float(h0));
        __nv_bfloat16 l1 = __float2bfloat16(v.y - __bfloat162float(h1));
        __nv_bfloat16 l2 = __float2bfloat16(v.z - __bfloat162float(h2));
        __nv_bfloat16 l3 = __float2bfloat16(v.w - __bfloat162float(h3));
        __nv_bfloat162 hA; hA.x = h0; hA.y = h1;
        __nv_bfloat162 hB; hB.x = h2; hB.y = h3;
        __nv_bfloat162 lA; lA.x = l0; lA.y = l1;
        __nv_bfloat162 lB; lB.x = l2; lB.y = l3;
        ((__nv_bfloat162*)hi)[2 * i]     = hA;
        ((__nv_bfloat162*)hi)[2 * i + 1] = hB;
        ((__nv_bfloat162*)lo)[2 * i]     = lA;
        ((__nv_bfloat162*)lo)[2 * i + 1] = lB;
    }
}

// ============================================================================
// GEMM: C[M,1024] = A[M,1024] @ W[1024,1024]^T + bias via 3-term bf16 split.
// CTA 128x128, BK=32, 256 thr, warp tile 32x64, cp.async double buffer.
// Smem rows padded to 80B: {80*r mod 128} = {0,80,32,112,64,16,96,48} ->
// all 8 distinct 16B slots -> conflict-free ldmatrix without XOR swizzle.
// blockIdx.z selects among up to 3 fused (W, bias, C) problem instances
// sharing the same A operand (Q/K/V projections).
// ============================================================================
static constexpr int BM = 128, BN = 128, BK = 32;
static constexpr int ROWB = 80;                   // padded row stride (bytes)
static constexpr int TILE_B = 128 * ROWB;         // 10240 B per tile
static constexpr int STAGE_B = 2 * TILE_B;        // A + B per stage
static constexpr int NCHUNK = EDIM / BK;          // 32
static constexpr int NIT = 3 * NCHUNK;            // 96 (3 split terms)

struct GemmJob {
    const __nv_bfloat16* Whi;
    const __nv_bfloat16* Wlo;
    const float* bias;
    float* C;
};

__global__ void __launch_bounds__(256)
gemm_split_kernel(const __nv_bfloat16* __restrict__ Ahi,
                  const __nv_bfloat16* __restrict__ Alo,
                  GemmJob j0, GemmJob j1, GemmJob j2) {
    const GemmJob job = (blockIdx.z == 0) ? j0 : (blockIdx.z == 1) ? j1 : j2;
    const __nv_bfloat16* __restrict__ Bhi = job.Whi;
    const __nv_bfloat16* __restrict__ Blo = job.Wlo;
    const float* __restrict__ bias = job.bias;
    float* __restrict__ C = job.C;

    __shared__ __align__(128) unsigned char smem[2 * STAGE_B];   // 40 KB
    const uint32_t sbase = smem_to_u32(smem);
    const int tid  = threadIdx.x;
    const int lane = tid & 31;
    const int w    = tid >> 5;
    const int m_off = (w >> 1) * 32;
    const int n_off = (w & 1) * 64;
    const int m0 = blockIdx.y * BM;
    const int n0 = blockIdx.x * BN;

    // ---- prefetch -------------------------------------------------------
    auto prefetch = [&](int it, int stage) {
        const int term = it >> 5;                 // /NCHUNK
        const int kc   = it & 31;
        const __nv_bfloat16* Ag = (term == 2) ? Alo : Ahi;   // hi,hi,lo
        const __nv_bfloat16* Bg = (term == 1) ? Blo : Bhi;   // hi,lo,hi
        const uint32_t sA = sbase + stage * STAGE_B;
        const uint32_t sB = sA + TILE_B;
        #pragma unroll
        for (int rep = 0; rep < 2; rep++) {
            int idx = tid + rep * 256;            // 0..511
            int r   = idx >> 2;                   // row 0..127
            int s   = idx & 3;                    // 16B segment
            cp16(sA + r * ROWB + s * 16,
                 Ag + (size_t)(m0 + r) * EDIM + kc * BK + s * 8);
            cp16(sB + r * ROWB + s * 16,
                 Bg + (size_t)(n0 + r) * EDIM + kc * BK + s * 8);
        }
        cp_commit();
    };

    float c[2][8][4];
    #pragma unroll
    for (int mi = 0; mi < 2; mi++)
        #pragma unroll
        for (int ni = 0; ni < 8; ni++)
            #pragma unroll
            for (int q = 0; q < 4; q++) c[mi][ni][q] = 0.f;

    prefetch(0, 0);

    for (int it = 0; it < NIT; it++) {
        if (it + 1 < NIT) {
            prefetch(it + 1, (it + 1) & 1);
            cp_wait1();
        } else {
            cp_wait0();
        }
        __syncthreads();

        const uint32_t sA = sbase + (it & 1) * STAGE_B;
        const uint32_t sB = sA + TILE_B;

        #pragma unroll
        for (int ks = 0; ks < 2; ks++) {          // two k16 steps in BK=32
            uint32_t a[2][4];
            #pragma unroll
            for (int mi = 0; mi < 2; mi++) {
                uint32_t addr = sA + (m_off + mi * 16 + (lane & 15)) * ROWB
                              + ks * 32 + ((lane >> 4) & 1) * 16;
                ldm_x4(a[mi], addr);
            }
            uint32_t b[8][2];
            #pragma unroll
            for (int ni = 0; ni < 4; ni++) {
                uint32_t r4[4];
                uint32_t addr = sB + (n_off + ni * 16 + ((lane >> 4) << 3) + (lane & 7)) * ROWB
                              + ks * 32 + ((lane >> 3) & 1) * 16;
                ldm_x4(r4, addr);
                b[2 * ni][0]     = r4[0]; b[2 * ni][1]     = r4[1];
                b[2 * ni + 1][0] = r4[2]; b[2 * ni + 1][1] = r4[3];
            }
            #pragma unroll
            for (int mi = 0; mi < 2; mi++)
                #pragma unroll
                for (int ni = 0; ni < 8; ni++)
                    mma_16816(c[mi][ni], a[mi], b[ni]);
        }
        __syncthreads();
    }

    // ---- epilogue: add bias, write fp32 ---------------------------------
    const int row0 = m0 + m_off + (lane >> 2);
    const int col0 = n0 + n_off + (lane & 3) * 2;
    #pragma unroll
    for (int ni = 0; ni < 8; ni++) {
        const int cL = col0 + ni * 8;
        const float b0 = bias[cL], b1 = bias[cL + 1];
        #pragma unroll
        for (int mi = 0; mi < 2; mi++) {
            const int r = row0 + mi * 16;
            float2 v0; v0.x = c[mi][ni][0] + b0; v0.y = c[mi][ni][1] + b1;
            *(float2*)(C + (size_t)r * EDIM + cL) = v0;
            float2 v1; v1.x = c[mi][ni][2] + b0; v1.y = c[mi][ni][3] + b1;
            *(float2*)(C + (size_t)(r + 8) * EDIM + cL) = v1;
        }
    }
}

// ============================================================================
// Attention: per position, scores = q k^T / 8 over the 16 heads, softmax,
// out = w v. One warp per position; output emitted as bf16 hi/lo split.
// ============================================================================
__global__ void __launch_bounds__(128)
attn_kernel(const float* __restrict__ Q, const float* __restrict__ K,
            const float* __restrict__ V,
            __nv_bfloat16* __restrict__ Ohi, __nv_bfloat16* __restrict__ Olo) {
    __shared__ float sk[4][1024];
    __shared__ float sv[4][1024];
    int w = threadIdx.x >> 5, lid = threadIdx.x & 31;
    int p = blockIdx.x * 4 + w;

    const float* kp = K + (size_t)p * 1024;
    const float* vp = V + (size_t)p * 1024;
    #pragma unroll
    for (int j = 0; j < 8; j++) {
        int idx = lid + j * 32;
        ((float4*)sk[w])[idx] = ((const float4*)kp)[idx];
        ((float4*)sv[w])[idx] = ((const float4*)vp)[idx];
    }
    __syncwarp();

    float wgt[16];
    #pragma unroll
    for (int j = 0; j < 16; j++) wgt[j] = 0.f;

    if (lid < 16) {
        const float* qp = Q + (size_t)p * 1024 + lid * 64;
        float q[64];
        #pragma unroll
        for (int j = 0; j < 16; j++) {
            float4 t = ((const float4*)qp)[j];
            q[4 * j] = t.x; q[4 * j + 1] = t.y; q[4 * j + 2] = t.z; q[4 * j + 3] = t.w;
        }
        float mx = -1e30f;
        #pragma unroll
        for (int j = 0; j < 16; j++) {
            float acc = 0.f;
            #pragma unroll
            for (int d4 = 0; d4 < 16; d4++) {
                float4 kv = ((const float4*)(&sk[w][j * 64]))[d4];
                acc += q[4 * d4] * kv.x + q[4 * d4 + 1] * kv.y
                     + q[4 * d4 + 2] * kv.z + q[4 * d4 + 3] * kv.w;
            }
            wgt[j] = acc * 0.125f;
            mx = fmaxf(mx, wgt[j]);
        }
        float sum = 0.f;
        #pragma unroll
        for (int j = 0; j < 16; j++) { wgt[j] = __expf(wgt[j] - mx); sum += wgt[j]; }
        float inv = 1.f / sum;
        #pragma unroll
        for (int j = 0; j < 16; j++) wgt[j] *= inv;
    }
    __syncwarp();

    int i = lid & 15;
    int dbase = (lid >> 4) * 32;
    float o[32];
    #pragma unroll
    for (int d = 0; d < 32; d++) o[d] = 0.f;
    #pragma unroll
    for (int j = 0; j < 16; j++) {
        float wj = __shfl_sync(0xffffffffu, wgt[j], i);
        #pragma unroll
        for (int d4 = 0; d4 < 8; d4++) {
            float4 vv = ((const float4*)(&sv[w][j * 64 + dbase]))[d4];
            o[4 * d4]     += wj * vv.x;
            o[4 * d4 + 1] += wj * vv.y;
            o[4 * d4 + 2] += wj * vv.z;
            o[4 * d4 + 3] += wj * vv.w;
        }
    }
    size_t ob = (size_t)p * 1024 + i * 64 + dbase;
    #pragma unroll
    for (int d2 = 0; d2 < 16; d2++) {
        float v0 = o[2 * d2], v1 = o[2 * d2 + 1];
        __nv_bfloat16 h0 = __float2bfloat16(v0);
        __nv_bfloat16 h1 = __float2bfloat16(v1);
        __nv_bfloat16 l0 = __float2bfloat16(v0 - __bfloat162float(h0));
        __nv_bfloat16 l1 = __float2bfloat16(v1 - __bfloat162float(h1));
        __nv_bfloat162 hh; hh.x = h0; hh.y = h1;
        __nv_bfloat162 ll; ll.x = l0; ll.y = l1;
        ((__nv_bfloat162*)(Ohi + ob))[d2] = hh;
        ((__nv_bfloat162*)(Olo + ob))[d2] = ll;
    }
}

// ============================================================================
// Launcher
// ============================================================================
extern "C" void kernel_launch(void* const* d_in, const int* in_sizes, int n_in,
                              void* d_out, int out_size) {
    const float* x  = (const float*)d_in[0];
    const float* wq = (const float*)d_in[1];
    const float* bq = (const float*)d_in[2];
    const float* wk = (const float*)d_in[3];
    const float* bk = (const float*)d_in[4];
    const float* wv = (const float*)d_in[5];
    const float* bv = (const float*)d_in[6];
    const float* wo = (const float*)d_in[7];
    const float* bo = (const float*)d_in[8];

    void *p;
    cudaGetSymbolAddress(&p, g_xhi); __nv_bfloat16* xhi = (__nv_bfloat16*)p;
    cudaGetSymbolAddress(&p, g_xlo); __nv_bfloat16* xlo = (__nv_bfloat16*)p;
    cudaGetSymbolAddress(&p, g_whi); __nv_bfloat16* whi = (__nv_bfloat16*)p;
    cudaGetSymbolAddress(&p, g_wlo); __nv_bfloat16* wlo = (__nv_bfloat16*)p;
    cudaGetSymbolAddress(&p, g_Q);   float* Qf = (float*)p;
    cudaGetSymbolAddress(&p, g_K);   float* Kf = (float*)p;
    cudaGetSymbolAddress(&p, g_V);   float* Vf = (float*)p;
    cudaGetSymbolAddress(&p, g_ahi); __nv_bfloat16* ahi = (__nv_bfloat16*)p;
    cudaGetSymbolAddress(&p, g_alo); __nv_bfloat16* alo = (__nv_bfloat16*)p;

    // 1. fp32 -> bf16 hi/lo splits
    split_kernel<<<2048, 256>>>((const float4*)x,  xhi, xlo, (int)(ACT_ELEMS / 4));
    split_kernel<<<512, 256>>>((const float4*)wq, whi + 0 * W_ELEMS, wlo + 0 * W_ELEMS, (int)(W_ELEMS / 4));
    split_kernel<<<512, 256>>>((const float4*)wk, whi + 1 * W_ELEMS, wlo + 1 * W_ELEMS, (int)(W_ELEMS / 4));
    split_kernel<<<512, 256>>>((const float4*)wv, whi + 2 * W_ELEMS, wlo + 2 * W_ELEMS, (int)(W_ELEMS / 4));
    split_kernel<<<512, 256>>>((const float4*)wo, whi + 3 * W_ELEMS, wlo + 3 * W_ELEMS, (int)(W_ELEMS / 4));

    // 2. Q/K/V projections fused into one launch (grid.z selects job);
    //    shared A tiles triple their L2 reuse across the three jobs.
    GemmJob jq{whi + 0 * W_ELEMS, wlo + 0 * W_ELEMS, bq, Qf};
    GemmJob jk{whi + 1 * W_ELEMS, wlo + 1 * W_ELEMS, bk, Kf};
    GemmJob jv{whi + 2 * W_ELEMS, wlo + 2 * W_ELEMS, bv, Vf};
    dim3 grid_qkv(EDIM / BN, MROWS / BM, 3);   // (8, 128, 3)
    gemm_split_kernel<<<grid_qkv, 256>>>(xhi, xlo, jq, jk, jv);

    // 3. Cross-head attention per position
    attn_kernel<<<MROWS / 4, 128>>>(Qf, Kf, Vf, ahi, alo);

    // 4. Output projection -> fp32 d_out
    GemmJob jo{whi + 3 * W_ELEMS, wlo + 3 * W_ELEMS, bo, (float*)d_out};
    dim3 grid_o(EDIM / BN, MROWS / BM, 1);
    gemm_split_kernel<<<grid_o, 256>>>(ahi, alo, jo, jo, jo);
}